// round 3
// baseline (speedup 1.0000x reference)
#include <cuda_runtime.h>
#include <math.h>

#define NB 4
#define NL 1024
#define NDM 1024
#define NH 16
#define NDK 64
#define NDV 64

// ---------------- device scratch (no runtime allocation allowed) ----------------
static __device__ float g_qh[(size_t)NB * NL * NDM];   // [B*L, H*DK]
static __device__ float g_kh[(size_t)NB * NL * NDM];
static __device__ float g_vh[(size_t)NB * NL * NDM];
static __device__ float g_ao[(size_t)NB * NL * NDM];   // attention output [B*L, H*DV]
static __device__ float g_y [(size_t)NB * NL * NDM];   // fc output (pre-LN)
static __device__ float g_attn[(size_t)NB * NH * NL * NL]; // fallback attn scratch (268MB)

// ---------------- packed fp32x2 helpers (sm_100+/sm_103a) ----------------
__device__ __forceinline__ unsigned long long pack_dup_f32(float x) {
    unsigned long long r;
    asm("mov.b64 %0, {%1, %1};" : "=l"(r) : "f"(x));
    return r;
}
__device__ __forceinline__ unsigned long long pack2_f32(float lo, float hi) {
    unsigned long long r;
    asm("mov.b64 %0, {%1, %2};" : "=l"(r) : "f"(lo), "f"(hi));
    return r;
}
__device__ __forceinline__ unsigned long long ffma2(
    unsigned long long a, unsigned long long b, unsigned long long c) {
    unsigned long long d;
    asm("fma.rn.f32x2 %0, %1, %2, %3;" : "=l"(d) : "l"(a), "l"(b), "l"(c));
    return d;
}
__device__ __forceinline__ float2 unpack2_f32(unsigned long long v) {
    float2 f;
    asm("mov.b64 {%0, %1}, %2;" : "=f"(f.x), "=f"(f.y) : "l"(v));
    return f;
}

// ---------------- SGEMM core: C[N,M] = A[N,K] @ W[M,K]^T + bias[M] ----------------
// 128x128 tile, K-step 8, 256 threads, 8x8 microtile, double-buffered smem.
// Inner product uses packed fp32x2 FMA: accumulators pack adjacent n-rows,
// B operand is stored DUPLICATED in smem so no per-iteration packing is needed.
__device__ __forceinline__ void sgemm_body(
    const float* __restrict__ A,
    const float* __restrict__ W,
    const float* __restrict__ bias,
    float* __restrict__ C,
    int M, int K,
    int mTile, int nTile)
{
    __shared__ float As[2][8][128];     // [k][n-row]
    __shared__ float Bs[2][8][256];     // [k][2*m-col] duplicated pairs

    const int t = threadIdx.x;
    const int tx = t & 15;   // m direction (8 cols each)
    const int ty = t >> 4;   // n direction (8 rows each)

    const int lr = t >> 1;          // 0..127, row within tile
    const int lk = (t & 1) * 4;     // k offset 0 or 4

    const float* Aptr = A + (size_t)(nTile + lr) * K + lk;
    const float* Wptr = W + (size_t)(mTile + lr) * K + lk;

    unsigned long long acc2[4][8];   // [n-row-pair][m-col]
    #pragma unroll
    for (int i = 0; i < 4; i++)
        #pragma unroll
        for (int j = 0; j < 8; j++) acc2[i][j] = 0ull;

    // prologue: stage 0
    {
        float4 a4 = *(const float4*)(Aptr);
        float4 b4 = *(const float4*)(Wptr);
        As[0][lk + 0][lr] = a4.x; As[0][lk + 1][lr] = a4.y;
        As[0][lk + 2][lr] = a4.z; As[0][lk + 3][lr] = a4.w;
        *(unsigned long long*)&Bs[0][lk + 0][2 * lr] = pack_dup_f32(b4.x);
        *(unsigned long long*)&Bs[0][lk + 1][2 * lr] = pack_dup_f32(b4.y);
        *(unsigned long long*)&Bs[0][lk + 2][2 * lr] = pack_dup_f32(b4.z);
        *(unsigned long long*)&Bs[0][lk + 3][2 * lr] = pack_dup_f32(b4.w);
    }
    __syncthreads();

    const int nIter = K / 8;
    int buf = 0;
    for (int it = 0; it < nIter; it++) {
        float4 a4n, b4n;
        const bool hasNext = (it + 1 < nIter);
        if (hasNext) {
            a4n = *(const float4*)(Aptr + (it + 1) * 8);
            b4n = *(const float4*)(Wptr + (it + 1) * 8);
        }

        #pragma unroll
        for (int kk = 0; kk < 8; kk++) {
            const ulonglong2* ap = (const ulonglong2*)&As[buf][kk][ty * 8];
            ulonglong2 a01 = ap[0];            // rows (0,1),(2,3)
            ulonglong2 a23 = ap[1];            // rows (4,5),(6,7)
            const ulonglong2* bp = (const ulonglong2*)&Bs[buf][kk][tx * 16];
            ulonglong2 b01 = bp[0];            // dup(b0), dup(b1)
            ulonglong2 b23 = bp[1];
            ulonglong2 b45 = bp[2];
            ulonglong2 b67 = bp[3];
            unsigned long long ap4[4] = {a01.x, a01.y, a23.x, a23.y};
            unsigned long long bd[8]  = {b01.x, b01.y, b23.x, b23.y,
                                         b45.x, b45.y, b67.x, b67.y};
            #pragma unroll
            for (int i = 0; i < 4; i++)
                #pragma unroll
                for (int j = 0; j < 8; j++)
                    acc2[i][j] = ffma2(ap4[i], bd[j], acc2[i][j]);
        }

        if (hasNext) {
            int nb = buf ^ 1;
            As[nb][lk + 0][lr] = a4n.x; As[nb][lk + 1][lr] = a4n.y;
            As[nb][lk + 2][lr] = a4n.z; As[nb][lk + 3][lr] = a4n.w;
            *(unsigned long long*)&Bs[nb][lk + 0][2 * lr] = pack_dup_f32(b4n.x);
            *(unsigned long long*)&Bs[nb][lk + 1][2 * lr] = pack_dup_f32(b4n.y);
            *(unsigned long long*)&Bs[nb][lk + 2][2 * lr] = pack_dup_f32(b4n.z);
            *(unsigned long long*)&Bs[nb][lk + 3][2 * lr] = pack_dup_f32(b4n.w);
            __syncthreads();
            buf = nb;
        }
    }

    float bv[8];
    #pragma unroll
    for (int j = 0; j < 8; j++) bv[j] = bias[mTile + tx * 8 + j];

    #pragma unroll
    for (int i2 = 0; i2 < 4; i2++) {
        float r0[8], r1[8];
        #pragma unroll
        for (int j = 0; j < 8; j++) {
            float2 p = unpack2_f32(acc2[i2][j]);
            r0[j] = p.x + bv[j];
            r1[j] = p.y + bv[j];
        }
        size_t off0 = (size_t)(nTile + ty * 8 + 2 * i2) * M + mTile + tx * 8;
        size_t off1 = off0 + M;
        *(float4*)(C + off0)     = make_float4(r0[0], r0[1], r0[2], r0[3]);
        *(float4*)(C + off0 + 4) = make_float4(r0[4], r0[5], r0[6], r0[7]);
        *(float4*)(C + off1)     = make_float4(r1[0], r1[1], r1[2], r1[3]);
        *(float4*)(C + off1 + 4) = make_float4(r1[4], r1[5], r1[6], r1[7]);
    }
}

// Fused Q/K/V projections in one launch (blockIdx.z selects projection) to
// remove per-launch wave tails.
__global__ __launch_bounds__(256) void qkv_gemm_kernel(
    const float* __restrict__ q, const float* __restrict__ k, const float* __restrict__ v,
    const float* __restrict__ w_q, const float* __restrict__ w_k, const float* __restrict__ w_v,
    const float* __restrict__ b_q, const float* __restrict__ b_k, const float* __restrict__ b_v,
    float* __restrict__ qh, float* __restrict__ kh, float* __restrict__ vh)
{
    const float* A;
    const float* W;
    const float* bias;
    float* C;
    if (blockIdx.z == 0)      { A = q; W = w_q; bias = b_q; C = qh; }
    else if (blockIdx.z == 1) { A = k; W = w_k; bias = b_k; C = kh; }
    else                      { A = v; W = w_v; bias = b_v; C = vh; }
    sgemm_body(A, W, bias, C, NDM, NDM, blockIdx.x * 128, blockIdx.y * 128);
}

__global__ __launch_bounds__(256) void sgemm_nt_bias(
    const float* __restrict__ A,
    const float* __restrict__ W,
    const float* __restrict__ bias,
    float* __restrict__ C,
    int M, int K)
{
    sgemm_body(A, W, bias, C, M, K, blockIdx.x * 128, blockIdx.y * 128);
}

// ---------------- Attention: per (b,h) 64-row q-tile, two passes ----------------
// Phase 1: S = (Q K^T / 8) * gate, masked -> -3e38; stream raw S to attn buffer
//          while keeping online row max m and sumexp l in registers (16-lane shfl).
// Phase 2: re-read S, p = exp(s-m)/l written in place (this IS the attn output),
//          accumulate O = P @ V in registers.
// Inner products use packed fp32x2 FMA (k-columns packed in pairs).
__global__ __launch_bounds__(256) void attn_kernel(
    const float* __restrict__ qh, const float* __restrict__ kh,
    const float* __restrict__ vh,
    const int* __restrict__ mask, const float* __restrict__ gate,
    float* __restrict__ attn, float* __restrict__ ao)
{
    __shared__ float SA[64][68];   // Q^T [d][i]  -> reused as P^T [j][i]
    __shared__ float SB[64][68];   // K^T [d][j]  -> reused as V   [j][dv]
    __shared__ float m_s[64];
    __shared__ float l_s[64];

    const int t  = threadIdx.x;
    const int tx = t & 15;
    const int ty = t >> 4;
    const int bh = blockIdx.y;           // 0..63
    const int b  = bh >> 4;
    const int h  = bh & 15;
    const int q0 = blockIdx.x * 64;

    const float* qbase = qh + ((size_t)(b * NL + q0)) * NDM + h * NDK;
    #pragma unroll
    for (int r = 0; r < 16; r++) {
        int idx = t + 256 * r;
        int l = idx >> 6, d = idx & 63;
        SA[d][l] = qbase[(size_t)l * NDM + d];
    }

    float m_run[4], l_run[4];
    #pragma unroll
    for (int i = 0; i < 4; i++) { m_run[i] = -3.0e38f; l_run[i] = 0.f; }

    const float* gbase = gate + ((size_t)bh * NL + q0) * NL;
    const int*   mbase = mask + ((size_t)b  * NL + q0) * NL;
    float*       abase = attn + ((size_t)bh * NL + q0) * NL;

    // -------- phase 1 --------
    for (int kt = 0; kt < 16; kt++) {
        const int k0 = kt * 64;
        const float* kbase = kh + ((size_t)(b * NL + k0)) * NDM + h * NDK;
        __syncthreads();
        #pragma unroll
        for (int r = 0; r < 16; r++) {
            int idx = t + 256 * r;
            int j = idx >> 6, d = idx & 63;
            SB[d][j] = kbase[(size_t)j * NDM + d];
        }
        __syncthreads();

        unsigned long long s2[4][2];   // [q-row][k-col-pair]
        #pragma unroll
        for (int i = 0; i < 4; i++) { s2[i][0] = 0ull; s2[i][1] = 0ull; }

        #pragma unroll
        for (int d = 0; d < 64; d++) {
            float4 qa = *(const float4*)&SA[d][ty * 4];
            ulonglong2 kb = *(const ulonglong2*)&SB[d][tx * 4]; // (k0,k1),(k2,k3)
            unsigned long long a0 = pack_dup_f32(qa.x);
            unsigned long long a1 = pack_dup_f32(qa.y);
            unsigned long long a2 = pack_dup_f32(qa.z);
            unsigned long long a3 = pack_dup_f32(qa.w);
            s2[0][0] = ffma2(a0, kb.x, s2[0][0]); s2[0][1] = ffma2(a0, kb.y, s2[0][1]);
            s2[1][0] = ffma2(a1, kb.x, s2[1][0]); s2[1][1] = ffma2(a1, kb.y, s2[1][1]);
            s2[2][0] = ffma2(a2, kb.x, s2[2][0]); s2[2][1] = ffma2(a2, kb.y, s2[2][1]);
            s2[3][0] = ffma2(a3, kb.x, s2[3][0]); s2[3][1] = ffma2(a3, kb.y, s2[3][1]);
        }

        #pragma unroll
        for (int ii = 0; ii < 4; ii++) {
            int gi = ty * 4 + ii;
            float2 sa = unpack2_f32(s2[ii][0]);
            float2 sb = unpack2_f32(s2[ii][1]);
            float4 g4 = *(const float4*)(gbase + (size_t)gi * NL + k0 + tx * 4);
            int4  mk4 = *(const int4*)  (mbase + (size_t)gi * NL + k0 + tx * 4);
            float v0 = (mk4.x > 0) ? -3.0e38f : sa.x * 0.125f * g4.x;
            float v1 = (mk4.y > 0) ? -3.0e38f : sa.y * 0.125f * g4.y;
            float v2 = (mk4.z > 0) ? -3.0e38f : sb.x * 0.125f * g4.z;
            float v3 = (mk4.w > 0) ? -3.0e38f : sb.y * 0.125f * g4.w;
            *(float4*)(abase + (size_t)gi * NL + k0 + tx * 4) =
                make_float4(v0, v1, v2, v3);

            float tmax = fmaxf(fmaxf(v0, v1), fmaxf(v2, v3));
            #pragma unroll
            for (int off = 1; off < 16; off <<= 1)
                tmax = fmaxf(tmax, __shfl_xor_sync(0xffffffffu, tmax, off));
            float mn = fmaxf(m_run[ii], tmax);

            float tsum = 0.f;
            tsum += (v0 > -1.0e37f) ? __expf(v0 - mn) : 0.f;
            tsum += (v1 > -1.0e37f) ? __expf(v1 - mn) : 0.f;
            tsum += (v2 > -1.0e37f) ? __expf(v2 - mn) : 0.f;
            tsum += (v3 > -1.0e37f) ? __expf(v3 - mn) : 0.f;
            #pragma unroll
            for (int off = 1; off < 16; off <<= 1)
                tsum += __shfl_xor_sync(0xffffffffu, tsum, off);

            float sc = (m_run[ii] > -1.0e37f) ? __expf(m_run[ii] - mn) : 0.f;
            l_run[ii] = l_run[ii] * sc + tsum;
            m_run[ii] = mn;
        }
    }

    if (tx == 0) {
        #pragma unroll
        for (int ii = 0; ii < 4; ii++) {
            m_s[ty * 4 + ii] = m_run[ii];
            l_s[ty * 4 + ii] = l_run[ii];
        }
    }
    __syncthreads();

    // -------- phase 2 --------
    unsigned long long o2[4][2];   // [q-row][dv-col-pair]
    #pragma unroll
    for (int i = 0; i < 4; i++) { o2[i][0] = 0ull; o2[i][1] = 0ull; }

    for (int kt = 0; kt < 16; kt++) {
        const int k0 = kt * 64;
        __syncthreads();
        const float* vbase = vh + ((size_t)(b * NL + k0)) * NDM + h * NDV;
        #pragma unroll
        for (int r = 0; r < 16; r++) {
            int idx = t + 256 * r;
            int j = idx >> 6, dv = idx & 63;
            SB[j][dv] = vbase[(size_t)j * NDM + dv];
        }
        #pragma unroll
        for (int r = 0; r < 4; r++) {
            int lin = t + 256 * r;            // float4 units over 64x64 tile
            int i = lin >> 4, j4 = lin & 15;
            float* ap = abase + (size_t)i * NL + k0 + j4 * 4;
            float4 sv = *(const float4*)ap;
            float mi  = m_s[i];
            float inv = 1.0f / l_s[i];
            float4 p;
            p.x = (sv.x > -1.0e37f) ? __expf(sv.x - mi) * inv : 0.f;
            p.y = (sv.y > -1.0e37f) ? __expf(sv.y - mi) * inv : 0.f;
            p.z = (sv.z > -1.0e37f) ? __expf(sv.z - mi) * inv : 0.f;
            p.w = (sv.w > -1.0e37f) ? __expf(sv.w - mi) * inv : 0.f;
            *(float4*)ap = p;
            SA[j4 * 4 + 0][i] = p.x;
            SA[j4 * 4 + 1][i] = p.y;
            SA[j4 * 4 + 2][i] = p.z;
            SA[j4 * 4 + 3][i] = p.w;
        }
        __syncthreads();
        #pragma unroll
        for (int j = 0; j < 64; j++) {
            float4 pa = *(const float4*)&SA[j][ty * 4];
            ulonglong2 vb = *(const ulonglong2*)&SB[j][tx * 4]; // (v0,v1),(v2,v3)
            unsigned long long p0 = pack_dup_f32(pa.x);
            unsigned long long p1 = pack_dup_f32(pa.y);
            unsigned long long p2 = pack_dup_f32(pa.z);
            unsigned long long p3 = pack_dup_f32(pa.w);
            o2[0][0] = ffma2(p0, vb.x, o2[0][0]); o2[0][1] = ffma2(p0, vb.y, o2[0][1]);
            o2[1][0] = ffma2(p1, vb.x, o2[1][0]); o2[1][1] = ffma2(p1, vb.y, o2[1][1]);
            o2[2][0] = ffma2(p2, vb.x, o2[2][0]); o2[2][1] = ffma2(p2, vb.y, o2[2][1]);
            o2[3][0] = ffma2(p3, vb.x, o2[3][0]); o2[3][1] = ffma2(p3, vb.y, o2[3][1]);
        }
    }

    float* obase = ao + ((size_t)(b * NL + q0)) * NDM + h * NDV;
    #pragma unroll
    for (int ii = 0; ii < 4; ii++) {
        float2 oa = unpack2_f32(o2[ii][0]);
        float2 ob = unpack2_f32(o2[ii][1]);
        *(float4*)(obase + (size_t)(ty * 4 + ii) * NDM + tx * 4) =
            make_float4(oa.x, oa.y, ob.x, ob.y);
    }
}

// ---------------- residual + LayerNorm ----------------
__global__ __launch_bounds__(256) void ln_kernel(
    const float* __restrict__ y, const float* __restrict__ res,
    const float* __restrict__ g, const float* __restrict__ be,
    float* __restrict__ out)
{
    __shared__ float red[8];
    const int row = blockIdx.x;
    const int t = threadIdx.x;
    const float* yr = y   + (size_t)row * NDM;
    const float* rr = res + (size_t)row * NDM;

    float x[4];
    float sum = 0.f;
    #pragma unroll
    for (int c = 0; c < 4; c++) {
        int idx = t + 256 * c;
        x[c] = yr[idx] + rr[idx];
        sum += x[c];
    }
    #pragma unroll
    for (int off = 16; off; off >>= 1) sum += __shfl_xor_sync(0xffffffffu, sum, off);
    if ((t & 31) == 0) red[t >> 5] = sum;
    __syncthreads();
    if (t == 0) {
        float s = 0.f;
        #pragma unroll
        for (int i = 0; i < 8; i++) s += red[i];
        red[0] = s;
    }
    __syncthreads();
    float mu = red[0] * (1.0f / NDM);
    __syncthreads();

    float vs = 0.f;
    #pragma unroll
    for (int c = 0; c < 4; c++) { float d = x[c] - mu; vs += d * d; }
    #pragma unroll
    for (int off = 16; off; off >>= 1) vs += __shfl_xor_sync(0xffffffffu, vs, off);
    if ((t & 31) == 0) red[t >> 5] = vs;
    __syncthreads();
    if (t == 0) {
        float s = 0.f;
        #pragma unroll
        for (int i = 0; i < 8; i++) s += red[i];
        red[0] = s;
    }
    __syncthreads();
    float rstd = rsqrtf(red[0] * (1.0f / NDM) + 1e-5f);

    #pragma unroll
    for (int c = 0; c < 4; c++) {
        int idx = t + 256 * c;
        out[(size_t)row * NDM + idx] = (x[c] - mu) * rstd * g[idx] + be[idx];
    }
}

// ---------------- launch ----------------
template <typename T>
static float* sym_addr(const T& sym) {
    void* p = nullptr;
    cudaGetSymbolAddress(&p, sym);
    return (float*)p;
}

extern "C" void kernel_launch(void* const* d_in, const int* in_sizes, int n_in,
                              void* d_out, int out_size) {
    (void)in_sizes; (void)n_in;
    const float* q    = (const float*)d_in[0];
    const float* k    = (const float*)d_in[1];
    const float* v    = (const float*)d_in[2];
    const int*   mask = (const int*)  d_in[3];
    const float* gate = (const float*)d_in[4];
    const float* w_q  = (const float*)d_in[5];
    const float* b_q  = (const float*)d_in[6];
    const float* w_k  = (const float*)d_in[7];
    const float* b_k  = (const float*)d_in[8];
    const float* w_v  = (const float*)d_in[9];
    const float* b_v  = (const float*)d_in[10];
    const float* w_fc = (const float*)d_in[11];
    const float* b_fc = (const float*)d_in[12];
    const float* ln_g = (const float*)d_in[13];
    const float* ln_b = (const float*)d_in[14];
    float* out = (float*)d_out;

    float* qh = sym_addr(g_qh);
    float* kh = sym_addr(g_kh);
    float* vh = sym_addr(g_vh);
    float* ao = sym_addr(g_ao);
    float* yv = sym_addr(g_y);

    const size_t outElems  = (size_t)NB * NL * NDM;            // 4194304
    const size_t attnElems = (size_t)NB * NH * NL * NL;        // 67108864
    float* attnbuf;
    if ((size_t)out_size >= outElems + attnElems)
        attnbuf = out + outElems;      // tuple order: (out, attn)
    else
        attnbuf = sym_addr(g_attn);    // attn not part of output -> scratch

    const dim3 qkvGrid(NDM / 128, (NB * NL) / 128, 3);   // (8, 32, 3) = 768 CTAs
    qkv_gemm_kernel<<<qkvGrid, 256>>>(q, k, v, w_q, w_k, w_v, b_q, b_k, b_v,
                                      qh, kh, vh);

    attn_kernel<<<dim3(NL / 64, NB * NH), 256>>>(qh, kh, vh, mask, gate, attnbuf, ao);

    const dim3 gemmGrid(NDM / 128, (NB * NL) / 128);
    sgemm_nt_bias<<<gemmGrid, 256>>>(ao, w_fc, b_fc, yv, NDM, NDM);

    ln_kernel<<<NB * NL, 256>>>(yv, q, ln_g, ln_b, out);
}

// round 4
// speedup vs baseline: 2.3158x; 2.3158x over previous
#include <cuda_runtime.h>
#include <math.h>

#define NB 4
#define NL 1024
#define NDM 1024
#define NH 16
#define NDK 64
#define NDV 64
#define KC 32

// ---------------- device scratch (no runtime allocation allowed) ----------------
static __device__ float g_qh[(size_t)NB * NL * NDM];   // [B*L, H*DK]
static __device__ float g_kh[(size_t)NB * NL * NDM];
static __device__ float g_vh[(size_t)NB * NL * NDM];
static __device__ float g_ao[(size_t)NB * NL * NDM];   // attention output [B*L, H*DV]
static __device__ float g_y [(size_t)NB * NL * NDM];   // fc output (pre-LN)
static __device__ float g_attn[(size_t)NB * NH * NL * NL]; // fallback attn scratch (268MB)

// ---------------- packed fp32x2 helpers (sm_100+/sm_103a) ----------------
__device__ __forceinline__ unsigned long long pack_dup_f32(float x) {
    unsigned long long r;
    asm("mov.b64 %0, {%1, %1};" : "=l"(r) : "f"(x));
    return r;
}
__device__ __forceinline__ unsigned long long ffma2(
    unsigned long long a, unsigned long long b, unsigned long long c) {
    unsigned long long d;
    asm("fma.rn.f32x2 %0, %1, %2, %3;" : "=l"(d) : "l"(a), "l"(b), "l"(c));
    return d;
}
__device__ __forceinline__ float2 unpack2_f32(unsigned long long v) {
    float2 f;
    asm("mov.b64 {%0, %1}, %2;" : "=f"(f.x), "=f"(f.y) : "l"(v));
    return f;
}

// XOR swizzle on float4-blocks within a 128-float smem row.
// fm = float4-block index (0..31), k4 = (k within chunk)>>2 (0..7).
// Guarantees: conflict-free LDS.128 fragment loads at fixed k, and
// conflict-free strided STS.32 chunk fills at fixed (warp-row, j).
__device__ __forceinline__ int swz(int fm, int k4) {
    return fm ^ ((fm >> 3) & 1) ^ k4;
}

// ---------------- SGEMM core: C[N,M] = A[N,K] @ W[M,K]^T + bias[M] ----------------
// 128x128 tile, kc=32 chunks, 256 threads, 8x8 microtile, FFMA2 inner loop.
// k-major smem with XOR swizzle; B operand duplicated in registers (not smem).
__device__ __forceinline__ void sgemm_body(
    const float* __restrict__ A,
    const float* __restrict__ W,
    const float* __restrict__ bias,
    float* __restrict__ C,
    int M, int K,
    int mTile, int nTile)
{
    __shared__ float As[KC * 128];   // [k][row], swizzled float4 blocks
    __shared__ float Ws[KC * 128];   // [k][col], swizzled float4 blocks

    const int t  = threadIdx.x;
    const int tx = t & 15;   // m direction (8 cols)
    const int ty = t >> 4;   // n direction (8 rows)

    // loader coords
    const int lk4 = t & 7;   // float4 index along k within chunk (k = lk4*4..+3)
    const int lr0 = t >> 3;  // base row 0..31 (rows lr0 + 32j)

    unsigned long long acc2[4][8];   // [row-pair][col]
    #pragma unroll
    for (int i = 0; i < 4; i++)
        #pragma unroll
        for (int j = 0; j < 8; j++) acc2[i][j] = 0ull;

    // precomputed fragment block indices (swizzle k-term applied per kk)
    const int fa0 = 2 * ty,     ea0 = (fa0 >> 3) & 1;
    const int fa1 = 2 * ty + 1, ea1 = (fa1 >> 3) & 1;
    const int fb0 = 2 * tx,     eb0 = (fb0 >> 3) & 1;
    const int fb1 = 2 * tx + 1, eb1 = (fb1 >> 3) & 1;

    const int nChunks = K / KC;
    for (int c = 0; c < nChunks; c++) {
        const int kc0 = c * KC;

        // ---- global loads (issued before barrier -> overlap prev compute) ----
        float4 av[4], wv[4];
        #pragma unroll
        for (int j = 0; j < 4; j++) {
            av[j] = *(const float4*)&A[(size_t)(nTile + lr0 + 32 * j) * K + kc0 + lk4 * 4];
            wv[j] = *(const float4*)&W[(size_t)(mTile + lr0 + 32 * j) * K + kc0 + lk4 * 4];
        }

        __syncthreads();   // prev chunk fully consumed

        // ---- store to swizzled k-major smem ----
        #pragma unroll
        for (int j = 0; j < 4; j++) {
            int row = lr0 + 32 * j;
            int fm  = row >> 2;
            int m0  = row & 3;
            int F   = swz(fm, lk4);
            float* pa = &As[(lk4 * 4) * 128 + F * 4 + m0];
            float* pw = &Ws[(lk4 * 4) * 128 + F * 4 + m0];
            pa[0 * 128] = av[j].x; pa[1 * 128] = av[j].y;
            pa[2 * 128] = av[j].z; pa[3 * 128] = av[j].w;
            pw[0 * 128] = wv[j].x; pw[1 * 128] = wv[j].y;
            pw[2 * 128] = wv[j].z; pw[3 * 128] = wv[j].w;
        }

        __syncthreads();   // chunk visible

        // ---- compute 32 k-steps ----
        #pragma unroll
        for (int kk = 0; kk < KC; kk++) {
            const int k4f  = kk >> 2;
            const int base = kk * 128;

            ulonglong2 a0 = *(const ulonglong2*)&As[base + ((fa0 ^ ea0 ^ k4f) << 2)];
            ulonglong2 a1 = *(const ulonglong2*)&As[base + ((fa1 ^ ea1 ^ k4f) << 2)];
            unsigned long long ar[4] = {a0.x, a0.y, a1.x, a1.y}; // row pairs (0,1)(2,3)(4,5)(6,7)

            float4 b0 = *(const float4*)&Ws[base + ((fb0 ^ eb0 ^ k4f) << 2)];
            float4 b1 = *(const float4*)&Ws[base + ((fb1 ^ eb1 ^ k4f) << 2)];
            unsigned long long bd[8];
            bd[0] = pack_dup_f32(b0.x); bd[1] = pack_dup_f32(b0.y);
            bd[2] = pack_dup_f32(b0.z); bd[3] = pack_dup_f32(b0.w);
            bd[4] = pack_dup_f32(b1.x); bd[5] = pack_dup_f32(b1.y);
            bd[6] = pack_dup_f32(b1.z); bd[7] = pack_dup_f32(b1.w);

            #pragma unroll
            for (int i = 0; i < 4; i++)
                #pragma unroll
                for (int j = 0; j < 8; j++)
                    acc2[i][j] = ffma2(ar[i], bd[j], acc2[i][j]);
        }
    }

    float bv[8];
    #pragma unroll
    for (int j = 0; j < 8; j++) bv[j] = bias[mTile + tx * 8 + j];

    #pragma unroll
    for (int i2 = 0; i2 < 4; i2++) {
        float r0[8], r1[8];
        #pragma unroll
        for (int j = 0; j < 8; j++) {
            float2 p = unpack2_f32(acc2[i2][j]);
            r0[j] = p.x + bv[j];
            r1[j] = p.y + bv[j];
        }
        size_t off0 = (size_t)(nTile + ty * 8 + 2 * i2) * M + mTile + tx * 8;
        size_t off1 = off0 + M;
        *(float4*)(C + off0)     = make_float4(r0[0], r0[1], r0[2], r0[3]);
        *(float4*)(C + off0 + 4) = make_float4(r0[4], r0[5], r0[6], r0[7]);
        *(float4*)(C + off1)     = make_float4(r1[0], r1[1], r1[2], r1[3]);
        *(float4*)(C + off1 + 4) = make_float4(r1[4], r1[5], r1[6], r1[7]);
    }
}

// Fused Q/K/V projections in one launch (blockIdx.z selects projection).
__global__ __launch_bounds__(256, 2) void qkv_gemm_kernel(
    const float* __restrict__ q, const float* __restrict__ k, const float* __restrict__ v,
    const float* __restrict__ w_q, const float* __restrict__ w_k, const float* __restrict__ w_v,
    const float* __restrict__ b_q, const float* __restrict__ b_k, const float* __restrict__ b_v,
    float* __restrict__ qh, float* __restrict__ kh, float* __restrict__ vh)
{
    const float* A;
    const float* W;
    const float* bias;
    float* C;
    if (blockIdx.z == 0)      { A = q; W = w_q; bias = b_q; C = qh; }
    else if (blockIdx.z == 1) { A = k; W = w_k; bias = b_k; C = kh; }
    else                      { A = v; W = w_v; bias = b_v; C = vh; }
    sgemm_body(A, W, bias, C, NDM, NDM, blockIdx.x * 128, blockIdx.y * 128);
}

__global__ __launch_bounds__(256, 2) void sgemm_nt_bias(
    const float* __restrict__ A,
    const float* __restrict__ W,
    const float* __restrict__ bias,
    float* __restrict__ C,
    int M, int K)
{
    sgemm_body(A, W, bias, C, M, K, blockIdx.x * 128, blockIdx.y * 128);
}

// ---------------- Attention: per (b,h) 64-row q-tile, two passes ----------------
// (unchanged from R3 passing version)
__global__ __launch_bounds__(256) void attn_kernel(
    const float* __restrict__ qh, const float* __restrict__ kh,
    const float* __restrict__ vh,
    const int* __restrict__ mask, const float* __restrict__ gate,
    float* __restrict__ attn, float* __restrict__ ao)
{
    __shared__ float SA[64][68];   // Q^T [d][i]  -> reused as P^T [j][i]
    __shared__ float SB[64][68];   // K^T [d][j]  -> reused as V   [j][dv]
    __shared__ float m_s[64];
    __shared__ float l_s[64];

    const int t  = threadIdx.x;
    const int tx = t & 15;
    const int ty = t >> 4;
    const int bh = blockIdx.y;           // 0..63
    const int b  = bh >> 4;
    const int h  = bh & 15;
    const int q0 = blockIdx.x * 64;

    const float* qbase = qh + ((size_t)(b * NL + q0)) * NDM + h * NDK;
    #pragma unroll
    for (int r = 0; r < 16; r++) {
        int idx = t + 256 * r;
        int l = idx >> 6, d = idx & 63;
        SA[d][l] = qbase[(size_t)l * NDM + d];
    }

    float m_run[4], l_run[4];
    #pragma unroll
    for (int i = 0; i < 4; i++) { m_run[i] = -3.0e38f; l_run[i] = 0.f; }

    const float* gbase = gate + ((size_t)bh * NL + q0) * NL;
    const int*   mbase = mask + ((size_t)b  * NL + q0) * NL;
    float*       abase = attn + ((size_t)bh * NL + q0) * NL;

    // -------- phase 1 --------
    for (int kt = 0; kt < 16; kt++) {
        const int k0 = kt * 64;
        const float* kbase = kh + ((size_t)(b * NL + k0)) * NDM + h * NDK;
        __syncthreads();
        #pragma unroll
        for (int r = 0; r < 16; r++) {
            int idx = t + 256 * r;
            int j = idx >> 6, d = idx & 63;
            SB[d][j] = kbase[(size_t)j * NDM + d];
        }
        __syncthreads();

        unsigned long long s2[4][2];   // [q-row][k-col-pair]
        #pragma unroll
        for (int i = 0; i < 4; i++) { s2[i][0] = 0ull; s2[i][1] = 0ull; }

        #pragma unroll
        for (int d = 0; d < 64; d++) {
            float4 qa = *(const float4*)&SA[d][ty * 4];
            ulonglong2 kb = *(const ulonglong2*)&SB[d][tx * 4]; // (k0,k1),(k2,k3)
            unsigned long long a0 = pack_dup_f32(qa.x);
            unsigned long long a1 = pack_dup_f32(qa.y);
            unsigned long long a2 = pack_dup_f32(qa.z);
            unsigned long long a3 = pack_dup_f32(qa.w);
            s2[0][0] = ffma2(a0, kb.x, s2[0][0]); s2[0][1] = ffma2(a0, kb.y, s2[0][1]);
            s2[1][0] = ffma2(a1, kb.x, s2[1][0]); s2[1][1] = ffma2(a1, kb.y, s2[1][1]);
            s2[2][0] = ffma2(a2, kb.x, s2[2][0]); s2[2][1] = ffma2(a2, kb.y, s2[2][1]);
            s2[3][0] = ffma2(a3, kb.x, s2[3][0]); s2[3][1] = ffma2(a3, kb.y, s2[3][1]);
        }

        #pragma unroll
        for (int ii = 0; ii < 4; ii++) {
            int gi = ty * 4 + ii;
            float2 sa = unpack2_f32(s2[ii][0]);
            float2 sb = unpack2_f32(s2[ii][1]);
            float4 g4 = *(const float4*)(gbase + (size_t)gi * NL + k0 + tx * 4);
            int4  mk4 = *(const int4*)  (mbase + (size_t)gi * NL + k0 + tx * 4);
            float v0 = (mk4.x > 0) ? -3.0e38f : sa.x * 0.125f * g4.x;
            float v1 = (mk4.y > 0) ? -3.0e38f : sa.y * 0.125f * g4.y;
            float v2 = (mk4.z > 0) ? -3.0e38f : sb.x * 0.125f * g4.z;
            float v3 = (mk4.w > 0) ? -3.0e38f : sb.y * 0.125f * g4.w;
            *(float4*)(abase + (size_t)gi * NL + k0 + tx * 4) =
                make_float4(v0, v1, v2, v3);

            float tmax = fmaxf(fmaxf(v0, v1), fmaxf(v2, v3));
            #pragma unroll
            for (int off = 1; off < 16; off <<= 1)
                tmax = fmaxf(tmax, __shfl_xor_sync(0xffffffffu, tmax, off));
            float mn = fmaxf(m_run[ii], tmax);

            float tsum = 0.f;
            tsum += (v0 > -1.0e37f) ? __expf(v0 - mn) : 0.f;
            tsum += (v1 > -1.0e37f) ? __expf(v1 - mn) : 0.f;
            tsum += (v2 > -1.0e37f) ? __expf(v2 - mn) : 0.f;
            tsum += (v3 > -1.0e37f) ? __expf(v3 - mn) : 0.f;
            #pragma unroll
            for (int off = 1; off < 16; off <<= 1)
                tsum += __shfl_xor_sync(0xffffffffu, tsum, off);

            float sc = (m_run[ii] > -1.0e37f) ? __expf(m_run[ii] - mn) : 0.f;
            l_run[ii] = l_run[ii] * sc + tsum;
            m_run[ii] = mn;
        }
    }

    if (tx == 0) {
        #pragma unroll
        for (int ii = 0; ii < 4; ii++) {
            m_s[ty * 4 + ii] = m_run[ii];
            l_s[ty * 4 + ii] = l_run[ii];
        }
    }
    __syncthreads();

    // -------- phase 2 --------
    unsigned long long o2[4][2];   // [q-row][dv-col-pair]
    #pragma unroll
    for (int i = 0; i < 4; i++) { o2[i][0] = 0ull; o2[i][1] = 0ull; }

    for (int kt = 0; kt < 16; kt++) {
        const int k0 = kt * 64;
        __syncthreads();
        const float* vbase = vh + ((size_t)(b * NL + k0)) * NDM + h * NDV;
        #pragma unroll
        for (int r = 0; r < 16; r++) {
            int idx = t + 256 * r;
            int j = idx >> 6, dv = idx & 63;
            SB[j][dv] = vbase[(size_t)j * NDM + dv];
        }
        #pragma unroll
        for (int r = 0; r < 4; r++) {
            int lin = t + 256 * r;            // float4 units over 64x64 tile
            int i = lin >> 4, j4 = lin & 15;
            float* ap = abase + (size_t)i * NL + k0 + j4 * 4;
            float4 sv = *(const float4*)ap;
            float mi  = m_s[i];
            float inv = 1.0f / l_s[i];
            float4 p;
            p.x = (sv.x > -1.0e37f) ? __expf(sv.x - mi) * inv : 0.f;
            p.y = (sv.y > -1.0e37f) ? __expf(sv.y - mi) * inv : 0.f;
            p.z = (sv.z > -1.0e37f) ? __expf(sv.z - mi) * inv : 0.f;
            p.w = (sv.w > -1.0e37f) ? __expf(sv.w - mi) * inv : 0.f;
            *(float4*)ap = p;
            SA[j4 * 4 + 0][i] = p.x;
            SA[j4 * 4 + 1][i] = p.y;
            SA[j4 * 4 + 2][i] = p.z;
            SA[j4 * 4 + 3][i] = p.w;
        }
        __syncthreads();
        #pragma unroll
        for (int j = 0; j < 64; j++) {
            float4 pa = *(const float4*)&SA[j][ty * 4];
            ulonglong2 vb = *(const ulonglong2*)&SB[j][tx * 4]; // (v0,v1),(v2,v3)
            unsigned long long p0 = pack_dup_f32(pa.x);
            unsigned long long p1 = pack_dup_f32(pa.y);
            unsigned long long p2 = pack_dup_f32(pa.z);
            unsigned long long p3 = pack_dup_f32(pa.w);
            o2[0][0] = ffma2(p0, vb.x, o2[0][0]); o2[0][1] = ffma2(p0, vb.y, o2[0][1]);
            o2[1][0] = ffma2(p1, vb.x, o2[1][0]); o2[1][1] = ffma2(p1, vb.y, o2[1][1]);
            o2[2][0] = ffma2(p2, vb.x, o2[2][0]); o2[2][1] = ffma2(p2, vb.y, o2[2][1]);
            o2[3][0] = ffma2(p3, vb.x, o2[3][0]); o2[3][1] = ffma2(p3, vb.y, o2[3][1]);
        }
    }

    float* obase = ao + ((size_t)(b * NL + q0)) * NDM + h * NDV;
    #pragma unroll
    for (int ii = 0; ii < 4; ii++) {
        float2 oa = unpack2_f32(o2[ii][0]);
        float2 ob = unpack2_f32(o2[ii][1]);
        *(float4*)(obase + (size_t)(ty * 4 + ii) * NDM + tx * 4) =
            make_float4(oa.x, oa.y, ob.x, ob.y);
    }
}

// ---------------- residual + LayerNorm ----------------
__global__ __launch_bounds__(256) void ln_kernel(
    const float* __restrict__ y, const float* __restrict__ res,
    const float* __restrict__ g, const float* __restrict__ be,
    float* __restrict__ out)
{
    __shared__ float red[8];
    const int row = blockIdx.x;
    const int t = threadIdx.x;
    const float* yr = y   + (size_t)row * NDM;
    const float* rr = res + (size_t)row * NDM;

    float x[4];
    float sum = 0.f;
    #pragma unroll
    for (int c = 0; c < 4; c++) {
        int idx = t + 256 * c;
        x[c] = yr[idx] + rr[idx];
        sum += x[c];
    }
    #pragma unroll
    for (int off = 16; off; off >>= 1) sum += __shfl_xor_sync(0xffffffffu, sum, off);
    if ((t & 31) == 0) red[t >> 5] = sum;
    __syncthreads();
    if (t == 0) {
        float s = 0.f;
        #pragma unroll
        for (int i = 0; i < 8; i++) s += red[i];
        red[0] = s;
    }
    __syncthreads();
    float mu = red[0] * (1.0f / NDM);
    __syncthreads();

    float vs = 0.f;
    #pragma unroll
    for (int c = 0; c < 4; c++) { float d = x[c] - mu; vs += d * d; }
    #pragma unroll
    for (int off = 16; off; off >>= 1) vs += __shfl_xor_sync(0xffffffffu, vs, off);
    if ((t & 31) == 0) red[t >> 5] = vs;
    __syncthreads();
    if (t == 0) {
        float s = 0.f;
        #pragma unroll
        for (int i = 0; i < 8; i++) s += red[i];
        red[0] = s;
    }
    __syncthreads();
    float rstd = rsqrtf(red[0] * (1.0f / NDM) + 1e-5f);

    #pragma unroll
    for (int c = 0; c < 4; c++) {
        int idx = t + 256 * c;
        out[(size_t)row * NDM + idx] = (x[c] - mu) * rstd * g[idx] + be[idx];
    }
}

// ---------------- launch ----------------
template <typename T>
static float* sym_addr(const T& sym) {
    void* p = nullptr;
    cudaGetSymbolAddress(&p, sym);
    return (float*)p;
}

extern "C" void kernel_launch(void* const* d_in, const int* in_sizes, int n_in,
                              void* d_out, int out_size) {
    (void)in_sizes; (void)n_in;
    const float* q    = (const float*)d_in[0];
    const float* k    = (const float*)d_in[1];
    const float* v    = (const float*)d_in[2];
    const int*   mask = (const int*)  d_in[3];
    const float* gate = (const float*)d_in[4];
    const float* w_q  = (const float*)d_in[5];
    const float* b_q  = (const float*)d_in[6];
    const float* w_k  = (const float*)d_in[7];
    const float* b_k  = (const float*)d_in[8];
    const float* w_v  = (const float*)d_in[9];
    const float* b_v  = (const float*)d_in[10];
    const float* w_fc = (const float*)d_in[11];
    const float* b_fc = (const float*)d_in[12];
    const float* ln_g = (const float*)d_in[13];
    const float* ln_b = (const float*)d_in[14];
    float* out = (float*)d_out;

    float* qh = sym_addr(g_qh);
    float* kh = sym_addr(g_kh);
    float* vh = sym_addr(g_vh);
    float* ao = sym_addr(g_ao);
    float* yv = sym_addr(g_y);

    const size_t outElems  = (size_t)NB * NL * NDM;            // 4194304
    const size_t attnElems = (size_t)NB * NH * NL * NL;        // 67108864
    float* attnbuf;
    if ((size_t)out_size >= outElems + attnElems)
        attnbuf = out + outElems;      // tuple order: (out, attn)
    else
        attnbuf = sym_addr(g_attn);    // attn not part of output -> scratch

    const dim3 qkvGrid(NDM / 128, (NB * NL) / 128, 3);   // (8, 32, 3) = 768 CTAs
    qkv_gemm_kernel<<<qkvGrid, 256>>>(q, k, v, w_q, w_k, w_v, b_q, b_k, b_v,
                                      qh, kh, vh);

    attn_kernel<<<dim3(NL / 64, NB * NH), 256>>>(qh, kh, vh, mask, gate, attnbuf, ao);

    const dim3 gemmGrid(NDM / 128, (NB * NL) / 128);
    sgemm_nt_bias<<<gemmGrid, 256>>>(ao, w_fc, b_fc, yv, NDM, NDM);

    ln_kernel<<<NB * NL, 256>>>(yv, q, ln_g, ln_b, out);
}